// round 5
// baseline (speedup 1.0000x reference)
#include <cuda_runtime.h>
#include <cuda_bf16.h>
#include <cstdint>

#define NTHREADS 128
#define T_MASK 524287u           // T = 2^19
#define HPI2 2654435761u
#define HPI3 805459861u

__device__ __constant__ int c_NL[16] =
    {16, 22, 30, 42, 58, 80, 110, 152, 210, 290, 400, 552, 762, 1052, 1452, 2004};

// ---- packed f32x2 helpers (Blackwell fma.rn.f32x2) ----
typedef unsigned long long u64;

__device__ __forceinline__ u64 pack2(float lo, float hi) {
    u64 r; asm("mov.b64 %0, {%1, %2};" : "=l"(r) : "f"(lo), "f"(hi)); return r;
}
__device__ __forceinline__ void unpack2(u64 v, float& lo, float& hi) {
    asm("mov.b64 {%0, %1}, %2;" : "=f"(lo), "=f"(hi) : "l"(v));
}
__device__ __forceinline__ u64 fma2(u64 a, u64 b, u64 c) {
    u64 r; asm("fma.rn.f32x2 %0, %1, %2, %3;" : "=l"(r) : "l"(a), "l"(b), "l"(c)); return r;
}

__device__ __forceinline__ float reduce_2pi(float x) {
    float k = rintf(x * 0.15915494309189535f);          // x / (2*pi)
    return fmaf(k, -6.283185307179586f, x);
}

__global__ __launch_bounds__(NTHREADS, 2) void ngp_fused_kernel(
    const float* __restrict__ x, const float* __restrict__ dirs,
    const float* __restrict__ tables,
    const float* __restrict__ w1, const float* __restrict__ b1,
    const float* __restrict__ w2, const float* __restrict__ b2,
    const float* __restrict__ w3, const float* __restrict__ b3,
    const float* __restrict__ w4, const float* __restrict__ b4,
    const float* __restrict__ w5, const float* __restrict__ b5,
    float* __restrict__ out, int N)
{
    __shared__ __align__(16) float s_w1[32 * 64];
    __shared__ __align__(16) float s_b1[64];
    __shared__ __align__(16) float s_w2[64 * 16];
    __shared__ __align__(16) float s_b2[16];
    __shared__ __align__(16) float s_w3[43 * 64];
    __shared__ __align__(16) float s_b3[64];
    __shared__ __align__(16) float s_w4t[64 * 64];   // transposed: [out][in]
    __shared__ __align__(16) float s_b4[64];
    __shared__ __align__(16) float s_w5[64 * 3];
    __shared__ __align__(16) float s_b5[3];

    for (int i = threadIdx.x; i < 32 * 64; i += NTHREADS) s_w1[i] = w1[i];
    for (int i = threadIdx.x; i < 64;      i += NTHREADS) s_b1[i] = b1[i];
    for (int i = threadIdx.x; i < 64 * 16; i += NTHREADS) s_w2[i] = w2[i];
    for (int i = threadIdx.x; i < 16;      i += NTHREADS) s_b2[i] = b2[i];
    for (int i = threadIdx.x; i < 43 * 64; i += NTHREADS) s_w3[i] = w3[i];
    for (int i = threadIdx.x; i < 64;      i += NTHREADS) s_b3[i] = b3[i];
    for (int i = threadIdx.x; i < 64 * 64; i += NTHREADS) {
        int r = i >> 6, c = i & 63;
        s_w4t[c * 64 + r] = w4[i];
    }
    for (int i = threadIdx.x; i < 64;      i += NTHREADS) s_b4[i] = b4[i];
    for (int i = threadIdx.x; i < 64 * 3;  i += NTHREADS) s_w5[i] = w5[i];
    for (int i = threadIdx.x; i < 3;       i += NTHREADS) s_b5[i] = b5[i];
    __syncthreads();

    // two points per thread: nA and nB = nA + NTHREADS
    const int nA = blockIdx.x * (2 * NTHREADS) + threadIdx.x;
    const int nB = nA + NTHREADS;
    if (nA >= N) return;
    const bool hasB = (nB < N);
    const int nBs = hasB ? nB : nA;   // safe index for loads

    // ---- position, AABB mask, [0,1) coords (both points) ----
    float x01[2][3];
    bool msk[2];
    {
        const int nn[2] = {nA, nBs};
        #pragma unroll
        for (int p = 0; p < 2; p++) {
            const float sx = x[3 * nn[p] + 0] * (1.0f / 3.0f);
            const float sy = x[3 * nn[p] + 1] * (1.0f / 3.0f);
            const float sz = x[3 * nn[p] + 2] * (1.0f / 3.0f);
            msk[p] = (fabsf(sx) < 0.5f) && (fabsf(sy) < 0.5f) && (fabsf(sz) < 0.5f);
            const float hi = 1.0f - 1e-7f;
            x01[p][0] = fminf(fmaxf(sx + 0.5f, 0.0f), hi);
            x01[p][1] = fminf(fmaxf(sy + 0.5f, 0.0f), hi);
            x01[p][2] = fminf(fmaxf(sz + 0.5f, 0.0f), hi);
        }
    }

    // ==== PHASE 1: all gathers -> features (no SMEM matvec interleaved) ====
    // feats[p][lvl] = packed (f0, f1)
    u64 feats[2][16];

    #pragma unroll
    for (int lvl = 0; lvl < 16; ++lvl) {
        const float res = (float)c_NL[lvl];
        const float2* tab = (const float2*)tables + (size_t)lvl * 524288u;
        #pragma unroll
        for (int p = 0; p < 2; p++) {
            const float fx = x01[p][0] * res, fy = x01[p][1] * res, fz = x01[p][2] * res;
            const float flx = floorf(fx), fly = floorf(fy), flz = floorf(fz);
            const float tx = fx - flx, ty = fy - fly, tz = fz - flz;
            const uint32_t X = (uint32_t)flx, Y = (uint32_t)fly, Z = (uint32_t)flz;

            // hoisted hash partials: y/z products once per level
            const uint32_t y0 = Y * HPI2, y1 = y0 + HPI2;
            const uint32_t z0 = Z * HPI3, z1 = z0 + HPI3;
            const uint32_t yz[4] = {y0 ^ z0, y1 ^ z0, y0 ^ z1, y1 ^ z1};

            float2 g[8];
            #pragma unroll
            for (int c = 0; c < 8; c++) {
                const uint32_t cx = c & 1u;
                const uint32_t h = (X + cx) ^ yz[c >> 1];
                g[c] = __ldg(&tab[h & T_MASK]);
            }
            const float wx[2] = {1.0f - tx, tx};
            const float wy[2] = {1.0f - ty, ty};
            const float wz[2] = {1.0f - tz, tz};
            float f0 = 0.0f, f1 = 0.0f;
            #pragma unroll
            for (int c = 0; c < 8; c++) {
                const float w = wx[c & 1u] * wy[(c >> 1) & 1u] * wz[(c >> 2) & 1u];
                f0 = fmaf(w, g[c].x, f0);
                f1 = fmaf(w, g[c].y, f1);
            }
            feats[p][lvl] = pack2(f0, f1);
        }
    }

    // ==== PHASE 2: density net. h1 processed in two 32-output halves,
    //      each half folded through ReLU into h2 immediately (h1 never fully live) ====
    u64 h2pA[8], h2pB[8];
    {
        const u64* b2p = (const u64*)s_b2;
        #pragma unroll
        for (int j = 0; j < 8; j++) { h2pA[j] = b2p[j]; h2pB[j] = b2p[j]; }
    }

    #pragma unroll
    for (int half = 0; half < 2; half++) {
        // accumulate h1[half*32 .. half*32+31] for both points
        u64 accA[16], accB[16];
        {
            const u64* b1p = (const u64*)s_b1 + half * 16;
            #pragma unroll
            for (int j = 0; j < 16; j++) { accA[j] = b1p[j]; accB[j] = b1p[j]; }
        }
        #pragma unroll
        for (int lvl = 0; lvl < 16; ++lvl) {
            float f0A, f1A, f0B, f1B;
            unpack2(feats[0][lvl], f0A, f1A);
            unpack2(feats[1][lvl], f0B, f1B);
            const u64 p0A = pack2(f0A, f0A), p1A = pack2(f1A, f1A);
            const u64 p0B = pack2(f0B, f0B), p1B = pack2(f1B, f1B);
            const ulonglong2* r0 = (const ulonglong2*)&s_w1[(2 * lvl + 0) * 64 + half * 32];
            const ulonglong2* r1 = (const ulonglong2*)&s_w1[(2 * lvl + 1) * 64 + half * 32];
            #pragma unroll
            for (int q = 0; q < 8; q++) {
                const ulonglong2 a = r0[q], b = r1[q];
                accA[2 * q + 0] = fma2(p0A, a.x, fma2(p1A, b.x, accA[2 * q + 0]));
                accA[2 * q + 1] = fma2(p0A, a.y, fma2(p1A, b.y, accA[2 * q + 1]));
                accB[2 * q + 0] = fma2(p0B, a.x, fma2(p1B, b.x, accB[2 * q + 0]));
                accB[2 * q + 1] = fma2(p0B, a.y, fma2(p1B, b.y, accB[2 * q + 1]));
            }
        }
        // ReLU this half and fold into h2 accumulators
        #pragma unroll
        for (int j = 0; j < 16; j++) {
            float aLo, aHi, bLo, bHi;
            unpack2(accA[j], aLo, aHi);
            unpack2(accB[j], bLo, bHi);
            const float vA[2] = {fmaxf(aLo, 0.0f), fmaxf(aHi, 0.0f)};
            const float vB[2] = {fmaxf(bLo, 0.0f), fmaxf(bHi, 0.0f)};
            #pragma unroll
            for (int s = 0; s < 2; s++) {
                const int i = half * 32 + 2 * j + s;     // global input index
                const u64 pA = pack2(vA[s], vA[s]);
                const u64 pB = pack2(vB[s], vB[s]);
                const ulonglong2* r = (const ulonglong2*)&s_w2[i * 16];
                #pragma unroll
                for (int q = 0; q < 4; q++) {
                    const ulonglong2 a = r[q];
                    h2pA[2 * q + 0] = fma2(pA, a.x, h2pA[2 * q + 0]);
                    h2pA[2 * q + 1] = fma2(pA, a.y, h2pA[2 * q + 1]);
                    h2pB[2 * q + 0] = fma2(pB, a.x, h2pB[2 * q + 0]);
                    h2pB[2 * q + 1] = fma2(pB, a.y, h2pB[2 * q + 1]);
                }
            }
        }
    }

    float h2A[16], h2B[16];
    #pragma unroll
    for (int j = 0; j < 8; j++) {
        unpack2(h2pA[j], h2A[2 * j], h2A[2 * j + 1]);
        unpack2(h2pB[j], h2B[2 * j], h2B[2 * j + 1]);
    }

    const float logSigA = msk[0] ? h2A[0] : -100000.0f;
    const float logSigB = msk[1] ? h2B[0] : -100000.0f;

    // ==== PHASE 3: color layer 1 (packed, shared weight reads) ====
    u64 c1pA[32], c1pB[32];
    {
        const u64* b3p = (const u64*)s_b3;
        #pragma unroll
        for (int j = 0; j < 32; j++) { c1pA[j] = b3p[j]; c1pB[j] = b3p[j]; }
    }

    float dvA[3], dvB[3];
    #pragma unroll
    for (int k = 0; k < 3; k++) { dvA[k] = dirs[3 * nA + k]; dvB[k] = dirs[3 * nBs + k]; }

    auto accum2 = [&](float vA, float vB, int row) {
        const u64 pA = pack2(vA, vA);
        const u64 pB = pack2(vB, vB);
        const ulonglong2* r = (const ulonglong2*)&s_w3[row * 64];
        #pragma unroll
        for (int q = 0; q < 16; q++) {
            const ulonglong2 a = r[q];
            c1pA[2 * q + 0] = fma2(pA, a.x, c1pA[2 * q + 0]);
            c1pA[2 * q + 1] = fma2(pA, a.y, c1pA[2 * q + 1]);
            c1pB[2 * q + 0] = fma2(pB, a.x, c1pB[2 * q + 0]);
            c1pB[2 * q + 1] = fma2(pB, a.y, c1pB[2 * q + 1]);
        }
    };

    #pragma unroll
    for (int k = 0; k < 3; k++) accum2(dvA[k], dvB[k], k);
    #pragma unroll
    for (int k = 0; k < 3; k++) {
        #pragma unroll
        for (int o = 0; o < 4; o++) {
            const float aA = reduce_2pi(dvA[k] * (float)(1 << o));
            const float aB = reduce_2pi(dvB[k] * (float)(1 << o));
            float sA, cA, sB, cB;
            sincosf(aA, &sA, &cA);
            sincosf(aB, &sB, &cB);
            accum2(sA, sB, 3 + k * 4 + o);
            accum2(cA, cB, 15 + k * 4 + o);
        }
    }
    #pragma unroll
    for (int j = 0; j < 16; j++) accum2(h2A[j], h2B[j], 27 + j);

    // ReLU c1 in packed form
    #pragma unroll
    for (int j = 0; j < 32; j++) {
        float lo, hh;
        unpack2(c1pA[j], lo, hh);
        c1pA[j] = pack2(fmaxf(lo, 0.0f), fmaxf(hh, 0.0f));
        unpack2(c1pB[j], lo, hh);
        c1pB[j] = pack2(fmaxf(lo, 0.0f), fmaxf(hh, 0.0f));
    }

    // ==== PHASE 4: color layer 2 + 3 (shared weight reads) ====
    float colA0 = s_b5[0], colA1 = s_b5[1], colA2 = s_b5[2];
    float colB0 = s_b5[0], colB1 = s_b5[1], colB2 = s_b5[2];
    #pragma unroll
    for (int j = 0; j < 64; j++) {
        const float bj = s_b4[j];
        u64 accA = pack2(bj, 0.0f);
        u64 accB = pack2(bj, 0.0f);
        const ulonglong2* r = (const ulonglong2*)&s_w4t[j * 64];
        #pragma unroll
        for (int q = 0; q < 16; q++) {
            const ulonglong2 a = r[q];
            accA = fma2(c1pA[2 * q + 0], a.x, accA);
            accA = fma2(c1pA[2 * q + 1], a.y, accA);
            accB = fma2(c1pB[2 * q + 0], a.x, accB);
            accB = fma2(c1pB[2 * q + 1], a.y, accB);
        }
        float lo, hh;
        unpack2(accA, lo, hh);
        const float aA = fmaxf(lo + hh, 0.0f);
        unpack2(accB, lo, hh);
        const float aB = fmaxf(lo + hh, 0.0f);
        const float w50 = s_w5[j * 3 + 0], w51 = s_w5[j * 3 + 1], w52 = s_w5[j * 3 + 2];
        colA0 = fmaf(aA, w50, colA0); colA1 = fmaf(aA, w51, colA1); colA2 = fmaf(aA, w52, colA2);
        colB0 = fmaf(aB, w50, colB0); colB1 = fmaf(aB, w51, colB1); colB2 = fmaf(aB, w52, colB2);
    }

    // sigmoid + mask + store
    colA0 = 1.0f / (1.0f + __expf(-colA0));
    colA1 = 1.0f / (1.0f + __expf(-colA1));
    colA2 = 1.0f / (1.0f + __expf(-colA2));
    if (!msk[0]) { colA0 = 0.0f; colA1 = 0.0f; colA2 = 0.0f; }
    out[3 * nA + 0] = colA0;
    out[3 * nA + 1] = colA1;
    out[3 * nA + 2] = colA2;
    out[3 * (size_t)N + nA] = logSigA;

    if (hasB) {
        colB0 = 1.0f / (1.0f + __expf(-colB0));
        colB1 = 1.0f / (1.0f + __expf(-colB1));
        colB2 = 1.0f / (1.0f + __expf(-colB2));
        if (!msk[1]) { colB0 = 0.0f; colB1 = 0.0f; colB2 = 0.0f; }
        out[3 * nB + 0] = colB0;
        out[3 * nB + 1] = colB1;
        out[3 * nB + 2] = colB2;
        out[3 * (size_t)N + nB] = logSigB;
    }
}

extern "C" void kernel_launch(void* const* d_in, const int* in_sizes, int n_in,
                              void* d_out, int out_size) {
    const float* x      = (const float*)d_in[0];
    const float* dirs   = (const float*)d_in[1];
    const float* tables = (const float*)d_in[2];
    const float* w1 = (const float*)d_in[3];
    const float* b1 = (const float*)d_in[4];
    const float* w2 = (const float*)d_in[5];
    const float* b2 = (const float*)d_in[6];
    const float* w3 = (const float*)d_in[7];
    const float* b3 = (const float*)d_in[8];
    const float* w4 = (const float*)d_in[9];
    const float* b4 = (const float*)d_in[10];
    const float* w5 = (const float*)d_in[11];
    const float* b5 = (const float*)d_in[12];
    float* out = (float*)d_out;

    const int N = in_sizes[0] / 3;
    const int blocks = (N + 2 * NTHREADS - 1) / (2 * NTHREADS);
    ngp_fused_kernel<<<blocks, NTHREADS>>>(x, dirs, tables,
                                           w1, b1, w2, b2, w3, b3, w4, b4, w5, b5,
                                           out, N);
}

// round 6
// speedup vs baseline: 1.5345x; 1.5345x over previous
#include <cuda_runtime.h>
#include <cuda_fp16.h>
#include <cstdint>

#define NT 128
#define T_MASK 524287u           // T = 2^19
#define HPI2 2654435761u
#define HPI3 805459861u
#define INV1024 0.0009765625f

__device__ __constant__ int c_NL[16] =
    {16, 22, 30, 42, 58, 80, 110, 152, 210, 290, 400, 552, 762, 1052, 1452, 2004};

__device__ __forceinline__ float reduce_2pi(float x) {
    float k = rintf(x * 0.15915494309189535f);
    return fmaf(k, -6.283185307179586f, x);
}

// m16n8k16 fp16 -> fp32 mma (canonical sm_80+ fragment layouts)
__device__ __forceinline__ void mma16816(float* d, const unsigned* a, unsigned b0, unsigned b1) {
    asm volatile(
        "mma.sync.aligned.m16n8k16.row.col.f32.f16.f16.f32 "
        "{%0,%1,%2,%3},{%4,%5,%6,%7},{%8,%9},{%0,%1,%2,%3};"
        : "+f"(d[0]), "+f"(d[1]), "+f"(d[2]), "+f"(d[3])
        : "r"(a[0]), "r"(a[1]), "r"(a[2]), "r"(a[3]), "r"(b0), "r"(b1));
}

__device__ __forceinline__ unsigned packh2(float lo, float hi) {
    __half2 h = __floats2half2_rn(lo, hi);
    return *reinterpret_cast<unsigned*>(&h);
}

__global__ __launch_bounds__(NT, 4) void ngp_tc_kernel(
    const float* __restrict__ x, const float* __restrict__ dirs,
    const float* __restrict__ tables,
    const float* __restrict__ w1, const float* __restrict__ b1,
    const float* __restrict__ w2, const float* __restrict__ b2,
    const float* __restrict__ w3, const float* __restrict__ b3,
    const float* __restrict__ w4, const float* __restrict__ b4,
    const float* __restrict__ w5, const float* __restrict__ b5,
    float* __restrict__ out, int N)
{
    // fp16 weights, transposed [out][in], rows padded for conflict-free B-frag LDS
    __shared__ __align__(16) __half s_w1h[64][40];
    __shared__ __align__(16) __half s_w2h[16][72];
    __shared__ __align__(16) __half s_w3h[64][56];
    __shared__ __align__(16) __half s_w4h[64][72];
    __shared__ __align__(16) __half s_w5h[8][72];
    __shared__ __align__(16) __half s_x32[128][36];  // hash features x 1024, fp16
    __shared__ __align__(16) __half s_xi[128][48];   // 0..26 direnc, 27=0, 28..43 h2, 44..47=0
    __shared__ float s_b1[64], s_b2[16], s_b3[64], s_b4[64], s_b5[8];
    __shared__ unsigned char s_mask[128];

    const int tid = threadIdx.x;

    // ---- stage fp16 weights (transposed, padded, w3 rows permuted to xi layout) ----
    for (int i = tid; i < 64 * 40; i += NT) {
        int n = i / 40, k = i % 40;
        s_w1h[n][k] = __float2half(k < 32 ? w1[k * 64 + n] : 0.0f);
    }
    for (int i = tid; i < 16 * 72; i += NT) {
        int n = i / 72, k = i % 72;
        s_w2h[n][k] = __float2half(k < 64 ? w2[k * 16 + n] : 0.0f);
    }
    for (int i = tid; i < 64 * 56; i += NT) {
        int n = i / 56, k = i % 56;
        float v = 0.0f;
        if (k < 27) v = w3[k * 64 + n];
        else if (k >= 28 && k < 44) v = w3[(k - 1) * 64 + n];  // h rows 27..42
        s_w3h[n][k] = __float2half(v);
    }
    for (int i = tid; i < 64 * 72; i += NT) {
        int n = i / 72, k = i % 72;
        s_w4h[n][k] = __float2half(k < 64 ? w4[k * 64 + n] : 0.0f);
    }
    for (int i = tid; i < 8 * 72; i += NT) {
        int n = i / 72, k = i % 72;
        s_w5h[n][k] = __float2half((n < 3 && k < 64) ? w5[k * 3 + n] : 0.0f);
    }
    if (tid < 64) { s_b1[tid] = b1[tid]; s_b3[tid] = b3[tid]; s_b4[tid] = b4[tid]; }
    if (tid < 16) s_b2[tid] = b2[tid];
    if (tid < 8)  s_b5[tid] = (tid < 3) ? b5[tid] : 0.0f;
    __syncthreads();

    // ================= ENCODE (per-thread, one point) =================
    const int n0 = blockIdx.x * NT + tid;
    const int nc = min(n0, N - 1);

    // zero my xi row (pads must be 0)
    {
        uint4 z = make_uint4(0, 0, 0, 0);
        uint4* zr = reinterpret_cast<uint4*>(&s_xi[tid][0]);
        #pragma unroll
        for (int i = 0; i < 6; i++) zr[i] = z;
    }

    {
        const float sx = x[3 * nc + 0] * (1.0f / 3.0f);
        const float sy = x[3 * nc + 1] * (1.0f / 3.0f);
        const float sz = x[3 * nc + 2] * (1.0f / 3.0f);
        const bool mk = (fabsf(sx) < 0.5f) && (fabsf(sy) < 0.5f) && (fabsf(sz) < 0.5f);
        s_mask[tid] = mk ? 1 : 0;
        const float hi = 1.0f - 1e-7f;
        const float x01x = fminf(fmaxf(sx + 0.5f, 0.0f), hi);
        const float x01y = fminf(fmaxf(sy + 0.5f, 0.0f), hi);
        const float x01z = fminf(fmaxf(sz + 0.5f, 0.0f), hi);

        #pragma unroll
        for (int lvl = 0; lvl < 16; ++lvl) {
            const float res = (float)c_NL[lvl];
            const float2* tab = (const float2*)tables + (size_t)lvl * 524288u;
            const float fx = x01x * res, fy = x01y * res, fz = x01z * res;
            const float flx = floorf(fx), fly = floorf(fy), flz = floorf(fz);
            const float tx = fx - flx, ty = fy - fly, tz = fz - flz;
            const uint32_t X = (uint32_t)flx, Y = (uint32_t)fly, Z = (uint32_t)flz;
            const uint32_t y0 = Y * HPI2, y1 = y0 + HPI2;
            const uint32_t z0 = Z * HPI3, z1 = z0 + HPI3;
            const uint32_t yz[4] = {y0 ^ z0, y1 ^ z0, y0 ^ z1, y1 ^ z1};

            float2 g[8];
            #pragma unroll
            for (int c = 0; c < 8; c++) {
                const uint32_t h = (X + (c & 1u)) ^ yz[c >> 1];
                g[c] = __ldg(&tab[h & T_MASK]);
            }
            const float wx[2] = {1.0f - tx, tx};
            const float wy[2] = {1.0f - ty, ty};
            const float wz[2] = {1.0f - tz, tz};
            float f0 = 0.0f, f1 = 0.0f;
            #pragma unroll
            for (int c = 0; c < 8; c++) {
                const float w = wx[c & 1u] * wy[(c >> 1) & 1u] * wz[(c >> 2) & 1u];
                f0 = fmaf(w, g[c].x, f0);
                f1 = fmaf(w, g[c].y, f1);
            }
            // scale by 2^10 (exact) to keep fp16 in its sweet spot; undone in L1 epilogue
            *reinterpret_cast<unsigned*>(&s_x32[tid][2 * lvl]) = packh2(f0 * 1024.0f, f1 * 1024.0f);
        }

        // direction encoding -> xi cols 0..26
        const float dv[3] = {dirs[3 * nc + 0], dirs[3 * nc + 1], dirs[3 * nc + 2]};
        s_xi[tid][0] = __float2half(dv[0]);
        s_xi[tid][1] = __float2half(dv[1]);
        s_xi[tid][2] = __float2half(dv[2]);
        #pragma unroll
        for (int k = 0; k < 3; k++) {
            #pragma unroll
            for (int o = 0; o < 4; o++) {
                const float ang = reduce_2pi(dv[k] * (float)(1 << o));
                float sv, cv;
                sincosf(ang, &sv, &cv);
                s_xi[tid][3 + k * 4 + o]  = __float2half(sv);
                s_xi[tid][15 + k * 4 + o] = __float2half(cv);
            }
        }
    }
    __syncwarp();

    // ================= MLP (per warp, 32 points, register-resident chain) =================
    const int warp = tid >> 5, lane = tid & 31;
    const int g2 = lane >> 2;        // 0..7
    const int c2 = (lane & 3) * 2;   // 0,2,4,6

#define LDU32(buf, r, c) (*reinterpret_cast<const unsigned*>(&buf[r][c]))

    #pragma unroll 1
    for (int m = 0; m < 2; m++) {
        const int r0 = (warp << 5) + (m << 4) + g2;   // local row for d0/d1
        const int r8 = r0 + 8;                        // local row for d2/d3

        // ---- L1: X32[.,32] @ W1 -> H[.,64] ----
        float dH[8][4] = {};
        #pragma unroll
        for (int kc = 0; kc < 2; kc++) {
            unsigned a[4];
            a[0] = LDU32(s_x32, r0, kc * 16 + c2);
            a[1] = LDU32(s_x32, r8, kc * 16 + c2);
            a[2] = LDU32(s_x32, r0, kc * 16 + c2 + 8);
            a[3] = LDU32(s_x32, r8, kc * 16 + c2 + 8);
            #pragma unroll
            for (int j = 0; j < 8; j++) {
                unsigned b0 = LDU32(s_w1h, j * 8 + g2, kc * 16 + c2);
                unsigned b1 = LDU32(s_w1h, j * 8 + g2, kc * 16 + c2 + 8);
                mma16816(dH[j], a, b0, b1);
            }
        }
        // epilogue: unscale + bias + relu -> A-frags for L2
        unsigned aH[4][4];
        #pragma unroll
        for (int kc = 0; kc < 4; kc++) {
            const int j0 = 2 * kc, j1 = j0 + 1;
            const float b00 = s_b1[8 * j0 + c2], b01 = s_b1[8 * j0 + c2 + 1];
            const float b10 = s_b1[8 * j1 + c2], b11 = s_b1[8 * j1 + c2 + 1];
            aH[kc][0] = packh2(fmaxf(fmaf(dH[j0][0], INV1024, b00), 0.0f),
                               fmaxf(fmaf(dH[j0][1], INV1024, b01), 0.0f));
            aH[kc][1] = packh2(fmaxf(fmaf(dH[j0][2], INV1024, b00), 0.0f),
                               fmaxf(fmaf(dH[j0][3], INV1024, b01), 0.0f));
            aH[kc][2] = packh2(fmaxf(fmaf(dH[j1][0], INV1024, b10), 0.0f),
                               fmaxf(fmaf(dH[j1][1], INV1024, b11), 0.0f));
            aH[kc][3] = packh2(fmaxf(fmaf(dH[j1][2], INV1024, b10), 0.0f),
                               fmaxf(fmaf(dH[j1][3], INV1024, b11), 0.0f));
        }

        // ---- L2: H @ W2 -> h2[.,16] (linear) ----
        float dS[2][4] = {};
        #pragma unroll
        for (int kc = 0; kc < 4; kc++) {
            #pragma unroll
            for (int j = 0; j < 2; j++) {
                unsigned b0 = LDU32(s_w2h, j * 8 + g2, kc * 16 + c2);
                unsigned b1 = LDU32(s_w2h, j * 8 + g2, kc * 16 + c2 + 8);
                mma16816(dS[j], aH[kc], b0, b1);
            }
        }
        // epilogue: +b2; write h2 -> xi cols 28..43; log_sigma from col 0
        #pragma unroll
        for (int j = 0; j < 2; j++) {
            const int c0 = 8 * j + c2;
            const float bb0 = s_b2[c0], bb1 = s_b2[c0 + 1];
            const float h0 = dS[j][0] + bb0, h1 = dS[j][1] + bb1;
            const float h2v = dS[j][2] + bb0, h3 = dS[j][3] + bb1;
            *reinterpret_cast<unsigned*>(&s_xi[r0][28 + c0]) = packh2(h0, h1);
            *reinterpret_cast<unsigned*>(&s_xi[r8][28 + c0]) = packh2(h2v, h3);
            if (j == 0 && c2 == 0) {
                const int p0 = blockIdx.x * NT + r0, p1 = p0 + 8;
                if (p0 < N) out[3 * (size_t)N + p0] = s_mask[r0] ? h0 : -100000.0f;
                if (p1 < N) out[3 * (size_t)N + p1] = s_mask[r8] ? h2v : -100000.0f;
            }
        }
        __syncwarp();

        // ---- L3: XI[.,48] @ W3 -> C1[.,64] ----
        float dC[8][4] = {};
        #pragma unroll
        for (int kc = 0; kc < 3; kc++) {
            unsigned a[4];
            a[0] = LDU32(s_xi, r0, kc * 16 + c2);
            a[1] = LDU32(s_xi, r8, kc * 16 + c2);
            a[2] = LDU32(s_xi, r0, kc * 16 + c2 + 8);
            a[3] = LDU32(s_xi, r8, kc * 16 + c2 + 8);
            #pragma unroll
            for (int j = 0; j < 8; j++) {
                unsigned b0 = LDU32(s_w3h, j * 8 + g2, kc * 16 + c2);
                unsigned b1 = LDU32(s_w3h, j * 8 + g2, kc * 16 + c2 + 8);
                mma16816(dC[j], a, b0, b1);
            }
        }
        unsigned aC[4][4];
        #pragma unroll
        for (int kc = 0; kc < 4; kc++) {
            const int j0 = 2 * kc, j1 = j0 + 1;
            const float b00 = s_b3[8 * j0 + c2], b01 = s_b3[8 * j0 + c2 + 1];
            const float b10 = s_b3[8 * j1 + c2], b11 = s_b3[8 * j1 + c2 + 1];
            aC[kc][0] = packh2(fmaxf(dC[j0][0] + b00, 0.0f), fmaxf(dC[j0][1] + b01, 0.0f));
            aC[kc][1] = packh2(fmaxf(dC[j0][2] + b00, 0.0f), fmaxf(dC[j0][3] + b01, 0.0f));
            aC[kc][2] = packh2(fmaxf(dC[j1][0] + b10, 0.0f), fmaxf(dC[j1][1] + b11, 0.0f));
            aC[kc][3] = packh2(fmaxf(dC[j1][2] + b10, 0.0f), fmaxf(dC[j1][3] + b11, 0.0f));
        }

        // ---- L4: C1 @ W4 -> C2[.,64] ----
        float dD[8][4] = {};
        #pragma unroll
        for (int kc = 0; kc < 4; kc++) {
            #pragma unroll
            for (int j = 0; j < 8; j++) {
                unsigned b0 = LDU32(s_w4h, j * 8 + g2, kc * 16 + c2);
                unsigned b1 = LDU32(s_w4h, j * 8 + g2, kc * 16 + c2 + 8);
                mma16816(dD[j], aC[kc], b0, b1);
            }
        }
        unsigned aD[4][4];
        #pragma unroll
        for (int kc = 0; kc < 4; kc++) {
            const int j0 = 2 * kc, j1 = j0 + 1;
            const float b00 = s_b4[8 * j0 + c2], b01 = s_b4[8 * j0 + c2 + 1];
            const float b10 = s_b4[8 * j1 + c2], b11 = s_b4[8 * j1 + c2 + 1];
            aD[kc][0] = packh2(fmaxf(dD[j0][0] + b00, 0.0f), fmaxf(dD[j0][1] + b01, 0.0f));
            aD[kc][1] = packh2(fmaxf(dD[j0][2] + b00, 0.0f), fmaxf(dD[j0][3] + b01, 0.0f));
            aD[kc][2] = packh2(fmaxf(dD[j1][0] + b10, 0.0f), fmaxf(dD[j1][1] + b11, 0.0f));
            aD[kc][3] = packh2(fmaxf(dD[j1][2] + b10, 0.0f), fmaxf(dD[j1][3] + b11, 0.0f));
        }

        // ---- L5: C2 @ W5 -> colors (cols 0..2 of 8) ----
        float dO[4] = {};
        #pragma unroll
        for (int kc = 0; kc < 4; kc++) {
            unsigned b0 = LDU32(s_w5h, g2, kc * 16 + c2);
            unsigned b1 = LDU32(s_w5h, g2, kc * 16 + c2 + 8);
            mma16816(dO, aD[kc], b0, b1);
        }
        {
            float v0 = dO[0] + s_b5[c2], v1 = dO[1] + s_b5[c2 + 1];
            float v2 = dO[2] + s_b5[c2], v3 = dO[3] + s_b5[c2 + 1];
            v0 = 1.0f / (1.0f + __expf(-v0));
            v1 = 1.0f / (1.0f + __expf(-v1));
            v2 = 1.0f / (1.0f + __expf(-v2));
            v3 = 1.0f / (1.0f + __expf(-v3));
            const int p0 = blockIdx.x * NT + r0, p1 = p0 + 8;
            const bool m0 = s_mask[r0], m1 = s_mask[r8];
            if (c2 == 0) {          // cols 0,1
                if (p0 < N) { out[3 * p0 + 0] = m0 ? v0 : 0.0f; out[3 * p0 + 1] = m0 ? v1 : 0.0f; }
                if (p1 < N) { out[3 * p1 + 0] = m1 ? v2 : 0.0f; out[3 * p1 + 1] = m1 ? v3 : 0.0f; }
            } else if (c2 == 2) {   // col 2
                if (p0 < N) out[3 * p0 + 2] = m0 ? v0 : 0.0f;
                if (p1 < N) out[3 * p1 + 2] = m1 ? v2 : 0.0f;
            }
        }
    }
#undef LDU32
}

extern "C" void kernel_launch(void* const* d_in, const int* in_sizes, int n_in,
                              void* d_out, int out_size) {
    const float* x      = (const float*)d_in[0];
    const float* dirs   = (const float*)d_in[1];
    const float* tables = (const float*)d_in[2];
    const float* w1 = (const float*)d_in[3];
    const float* b1 = (const float*)d_in[4];
    const float* w2 = (const float*)d_in[5];
    const float* b2 = (const float*)d_in[6];
    const float* w3 = (const float*)d_in[7];
    const float* b3 = (const float*)d_in[8];
    const float* w4 = (const float*)d_in[9];
    const float* b4 = (const float*)d_in[10];
    const float* w5 = (const float*)d_in[11];
    const float* b5 = (const float*)d_in[12];
    float* out = (float*)d_out;

    const int N = in_sizes[0] / 3;
    const int blocks = (N + NT - 1) / NT;
    ngp_tc_kernel<<<blocks, NT>>>(x, dirs, tables,
                                  w1, b1, w2, b2, w3, b3, w4, b4, w5, b5,
                                  out, N);
}

// round 13
// speedup vs baseline: 1.6872x; 1.0995x over previous
#include <cuda_runtime.h>
#include <cuda_fp16.h>
#include <cstdint>

#define NT 128
#define T_MASK 524287u           // T = 2^19
#define HPI2 2654435761u
#define HPI3 805459861u
#define INV1024 0.0009765625f

__device__ __constant__ int c_NL[16] =
    {16, 22, 30, 42, 58, 80, 110, 152, 210, 290, 400, 552, 762, 1052, 1452, 2004};

__device__ __forceinline__ float reduce_2pi(float x) {
    float k = rintf(x * 0.15915494309189535f);
    return fmaf(k, -6.283185307179586f, x);
}

// m16n8k16 fp16 -> fp32 mma (canonical sm_80+ fragment layouts)
__device__ __forceinline__ void mma16816(float* d, const unsigned* a, unsigned b0, unsigned b1) {
    asm volatile(
        "mma.sync.aligned.m16n8k16.row.col.f32.f16.f16.f32 "
        "{%0,%1,%2,%3},{%4,%5,%6,%7},{%8,%9},{%0,%1,%2,%3};"
        : "+f"(d[0]), "+f"(d[1]), "+f"(d[2]), "+f"(d[3])
        : "r"(a[0]), "r"(a[1]), "r"(a[2]), "r"(a[3]), "r"(b0), "r"(b1));
}

__device__ __forceinline__ unsigned packh2(float lo, float hi) {
    __half2 h = __floats2half2_rn(lo, hi);
    return *reinterpret_cast<unsigned*>(&h);
}

__global__ __launch_bounds__(NT, 4) void ngp_tc_kernel(
    const float* __restrict__ x, const float* __restrict__ dirs,
    const float* __restrict__ tables,
    const float* __restrict__ w1, const float* __restrict__ b1,
    const float* __restrict__ w2, const float* __restrict__ b2,
    const float* __restrict__ w3, const float* __restrict__ b3,
    const float* __restrict__ w4, const float* __restrict__ b4,
    const float* __restrict__ w5, const float* __restrict__ b5,
    float* __restrict__ out, int N)
{
    // fp16 weights, transposed [out][in], rows padded for conflict-free B-frag LDS
    __shared__ __align__(16) __half s_w1h[64][40];
    __shared__ __align__(16) __half s_w2h[16][72];
    __shared__ __align__(16) __half s_w3h[64][56];
    __shared__ __align__(16) __half s_w4h[64][72];
    __shared__ __align__(16) __half s_w5h[8][72];
    __shared__ __align__(16) __half s_x32[128][36];  // hash features x 1024, fp16
    __shared__ __align__(16) __half s_xi[128][48];   // 0..26 direnc, 27=0, 28..43 h2, 44..47=0
    __shared__ float s_b1[64], s_b2[16], s_b3[64], s_b4[64], s_b5[8];
    __shared__ unsigned char s_mask[128];

    const int tid = threadIdx.x;

    // ---- stage fp16 weights (transposed, padded, w3 rows permuted to xi layout) ----
    for (int i = tid; i < 64 * 40; i += NT) {
        int n = i / 40, k = i % 40;
        s_w1h[n][k] = __float2half(k < 32 ? w1[k * 64 + n] : 0.0f);
    }
    for (int i = tid; i < 16 * 72; i += NT) {
        int n = i / 72, k = i % 72;
        s_w2h[n][k] = __float2half(k < 64 ? w2[k * 16 + n] : 0.0f);
    }
    for (int i = tid; i < 64 * 56; i += NT) {
        int n = i / 56, k = i % 56;
        float v = 0.0f;
        if (k < 27) v = w3[k * 64 + n];
        else if (k >= 28 && k < 44) v = w3[(k - 1) * 64 + n];  // h rows 27..42
        s_w3h[n][k] = __float2half(v);
    }
    for (int i = tid; i < 64 * 72; i += NT) {
        int n = i / 72, k = i % 72;
        s_w4h[n][k] = __float2half(k < 64 ? w4[k * 64 + n] : 0.0f);
    }
    for (int i = tid; i < 8 * 72; i += NT) {
        int n = i / 72, k = i % 72;
        s_w5h[n][k] = __float2half((n < 3 && k < 64) ? w5[k * 3 + n] : 0.0f);
    }
    if (tid < 64) { s_b1[tid] = b1[tid]; s_b3[tid] = b3[tid]; s_b4[tid] = b4[tid]; }
    if (tid < 16) s_b2[tid] = b2[tid];
    if (tid < 8)  s_b5[tid] = (tid < 3) ? b5[tid] : 0.0f;
    __syncthreads();

    // ================= ENCODE (per-thread, one point) =================
    const int n0 = blockIdx.x * NT + tid;
    const int nc = min(n0, N - 1);

    // zero my xi row (pads must be 0)
    {
        uint4 z = make_uint4(0, 0, 0, 0);
        uint4* zr = reinterpret_cast<uint4*>(&s_xi[tid][0]);
        #pragma unroll
        for (int i = 0; i < 6; i++) zr[i] = z;
    }

    {
        const float sx = x[3 * nc + 0] * (1.0f / 3.0f);
        const float sy = x[3 * nc + 1] * (1.0f / 3.0f);
        const float sz = x[3 * nc + 2] * (1.0f / 3.0f);
        const bool mk = (fabsf(sx) < 0.5f) && (fabsf(sy) < 0.5f) && (fabsf(sz) < 0.5f);
        s_mask[tid] = mk ? 1 : 0;
        const float hi = 1.0f - 1e-7f;
        const float x01x = fminf(fmaxf(sx + 0.5f, 0.0f), hi);
        const float x01y = fminf(fmaxf(sy + 0.5f, 0.0f), hi);
        const float x01z = fminf(fmaxf(sz + 0.5f, 0.0f), hi);

        #pragma unroll
        for (int lvl = 0; lvl < 16; ++lvl) {
            const float res = (float)c_NL[lvl];
            const float2* tab = (const float2*)tables + (size_t)lvl * 524288u;
            const float fx = x01x * res, fy = x01y * res, fz = x01z * res;
            const float flx = floorf(fx), fly = floorf(fy), flz = floorf(fz);
            const float tx = fx - flx, ty = fy - fly, tz = fz - flz;
            const uint32_t X = (uint32_t)flx, Y = (uint32_t)fly, Z = (uint32_t)flz;
            const uint32_t y0 = Y * HPI2, y1 = y0 + HPI2;
            const uint32_t z0 = Z * HPI3, z1 = z0 + HPI3;
            const uint32_t yz[4] = {y0 ^ z0, y1 ^ z0, y0 ^ z1, y1 ^ z1};

            // corner gathers; when X is even, h(X+1)=h(X)^1 -> the two corners of
            // each x-pair live in one 16B-aligned float4 slot: 4 loads instead of 8.
            float2 g[8];
            if ((X & 1u) == 0u) {
                #pragma unroll
                for (int p2 = 0; p2 < 4; p2++) {
                    const uint32_t h0 = X ^ yz[p2];
                    const uint32_t base = (h0 & ~1u) & T_MASK;
                    const float4 q = __ldg(reinterpret_cast<const float4*>(&tab[base]));
                    const bool hiHalf = (h0 & 1u);
                    g[2 * p2 + 0] = hiHalf ? make_float2(q.z, q.w) : make_float2(q.x, q.y);
                    g[2 * p2 + 1] = hiHalf ? make_float2(q.x, q.y) : make_float2(q.z, q.w);
                }
            } else {
                #pragma unroll
                for (int p2 = 0; p2 < 4; p2++) {
                    g[2 * p2 + 0] = __ldg(&tab[(X ^ yz[p2]) & T_MASK]);
                    g[2 * p2 + 1] = __ldg(&tab[((X + 1u) ^ yz[p2]) & T_MASK]);
                }
            }

            const float wx[2] = {1.0f - tx, tx};
            const float wy[2] = {1.0f - ty, ty};
            const float wz[2] = {1.0f - tz, tz};
            float f0 = 0.0f, f1 = 0.0f;
            #pragma unroll
            for (int c = 0; c < 8; c++) {
                const float w = wx[c & 1u] * wy[(c >> 1) & 1u] * wz[(c >> 2) & 1u];
                f0 = fmaf(w, g[c].x, f0);
                f1 = fmaf(w, g[c].y, f1);
            }
            // scale by 2^10 (exact) to keep fp16 in its sweet spot; undone in L1 epilogue
            *reinterpret_cast<unsigned*>(&s_x32[tid][2 * lvl]) = packh2(f0 * 1024.0f, f1 * 1024.0f);
        }

        // direction encoding -> xi cols 0..26
        const float dv[3] = {dirs[3 * nc + 0], dirs[3 * nc + 1], dirs[3 * nc + 2]};
        s_xi[tid][0] = __float2half(dv[0]);
        s_xi[tid][1] = __float2half(dv[1]);
        s_xi[tid][2] = __float2half(dv[2]);
        #pragma unroll
        for (int k = 0; k < 3; k++) {
            #pragma unroll
            for (int o = 0; o < 4; o++) {
                const float ang = reduce_2pi(dv[k] * (float)(1 << o));
                float sv, cv;
                sincosf(ang, &sv, &cv);
                s_xi[tid][3 + k * 4 + o]  = __float2half(sv);
                s_xi[tid][15 + k * 4 + o] = __float2half(cv);
            }
        }
    }
    __syncwarp();

    // ================= MLP (per warp, 32 points, register-resident chain) =================
    const int warp = tid >> 5, lane = tid & 31;
    const int g2 = lane >> 2;        // 0..7
    const int c2 = (lane & 3) * 2;   // 0,2,4,6

#define LDU32(buf, r, c) (*reinterpret_cast<const unsigned*>(&buf[r][c]))

    #pragma unroll 1
    for (int m = 0; m < 2; m++) {
        const int r0 = (warp << 5) + (m << 4) + g2;   // local row for d0/d1
        const int r8 = r0 + 8;                        // local row for d2/d3

        // ---- L1: X32[.,32] @ W1 -> H[.,64] ----
        float dH[8][4] = {};
        #pragma unroll
        for (int kc = 0; kc < 2; kc++) {
            unsigned a[4];
            a[0] = LDU32(s_x32, r0, kc * 16 + c2);
            a[1] = LDU32(s_x32, r8, kc * 16 + c2);
            a[2] = LDU32(s_x32, r0, kc * 16 + c2 + 8);
            a[3] = LDU32(s_x32, r8, kc * 16 + c2 + 8);
            #pragma unroll
            for (int j = 0; j < 8; j++) {
                unsigned b0 = LDU32(s_w1h, j * 8 + g2, kc * 16 + c2);
                unsigned b1 = LDU32(s_w1h, j * 8 + g2, kc * 16 + c2 + 8);
                mma16816(dH[j], a, b0, b1);
            }
        }
        // epilogue: unscale + bias + relu -> A-frags for L2
        unsigned aH[4][4];
        #pragma unroll
        for (int kc = 0; kc < 4; kc++) {
            const int j0 = 2 * kc, j1 = j0 + 1;
            const float b00 = s_b1[8 * j0 + c2], b01 = s_b1[8 * j0 + c2 + 1];
            const float b10 = s_b1[8 * j1 + c2], b11 = s_b1[8 * j1 + c2 + 1];
            aH[kc][0] = packh2(fmaxf(fmaf(dH[j0][0], INV1024, b00), 0.0f),
                               fmaxf(fmaf(dH[j0][1], INV1024, b01), 0.0f));
            aH[kc][1] = packh2(fmaxf(fmaf(dH[j0][2], INV1024, b00), 0.0f),
                               fmaxf(fmaf(dH[j0][3], INV1024, b01), 0.0f));
            aH[kc][2] = packh2(fmaxf(fmaf(dH[j1][0], INV1024, b10), 0.0f),
                               fmaxf(fmaf(dH[j1][1], INV1024, b11), 0.0f));
            aH[kc][3] = packh2(fmaxf(fmaf(dH[j1][2], INV1024, b10), 0.0f),
                               fmaxf(fmaf(dH[j1][3], INV1024, b11), 0.0f));
        }

        // ---- L2: H @ W2 -> h2[.,16] (linear) ----
        float dS[2][4] = {};
        #pragma unroll
        for (int kc = 0; kc < 4; kc++) {
            #pragma unroll
            for (int j = 0; j < 2; j++) {
                unsigned b0 = LDU32(s_w2h, j * 8 + g2, kc * 16 + c2);
                unsigned b1 = LDU32(s_w2h, j * 8 + g2, kc * 16 + c2 + 8);
                mma16816(dS[j], aH[kc], b0, b1);
            }
        }
        // epilogue: +b2; write h2 -> xi cols 28..43; log_sigma from col 0
        #pragma unroll
        for (int j = 0; j < 2; j++) {
            const int c0 = 8 * j + c2;
            const float bb0 = s_b2[c0], bb1 = s_b2[c0 + 1];
            const float h0 = dS[j][0] + bb0, h1 = dS[j][1] + bb1;
            const float h2v = dS[j][2] + bb0, h3 = dS[j][3] + bb1;
            *reinterpret_cast<unsigned*>(&s_xi[r0][28 + c0]) = packh2(h0, h1);
            *reinterpret_cast<unsigned*>(&s_xi[r8][28 + c0]) = packh2(h2v, h3);
            if (j == 0 && c2 == 0) {
                const int p0 = blockIdx.x * NT + r0, p1 = p0 + 8;
                if (p0 < N) out[3 * (size_t)N + p0] = s_mask[r0] ? h0 : -100000.0f;
                if (p1 < N) out[3 * (size_t)N + p1] = s_mask[r8] ? h2v : -100000.0f;
            }
        }
        __syncwarp();

        // ---- L3: XI[.,48] @ W3 -> C1[.,64] ----
        float dC[8][4] = {};
        #pragma unroll
        for (int kc = 0; kc < 3; kc++) {
            unsigned a[4];
            a[0] = LDU32(s_xi, r0, kc * 16 + c2);
            a[1] = LDU32(s_xi, r8, kc * 16 + c2);
            a[2] = LDU32(s_xi, r0, kc * 16 + c2 + 8);
            a[3] = LDU32(s_xi, r8, kc * 16 + c2 + 8);
            #pragma unroll
            for (int j = 0; j < 8; j++) {
                unsigned b0 = LDU32(s_w3h, j * 8 + g2, kc * 16 + c2);
                unsigned b1 = LDU32(s_w3h, j * 8 + g2, kc * 16 + c2 + 8);
                mma16816(dC[j], a, b0, b1);
            }
        }
        unsigned aC[4][4];
        #pragma unroll
        for (int kc = 0; kc < 4; kc++) {
            const int j0 = 2 * kc, j1 = j0 + 1;
            const float b00 = s_b3[8 * j0 + c2], b01 = s_b3[8 * j0 + c2 + 1];
            const float b10 = s_b3[8 * j1 + c2], b11 = s_b3[8 * j1 + c2 + 1];
            aC[kc][0] = packh2(fmaxf(dC[j0][0] + b00, 0.0f), fmaxf(dC[j0][1] + b01, 0.0f));
            aC[kc][1] = packh2(fmaxf(dC[j0][2] + b00, 0.0f), fmaxf(dC[j0][3] + b01, 0.0f));
            aC[kc][2] = packh2(fmaxf(dC[j1][0] + b10, 0.0f), fmaxf(dC[j1][1] + b11, 0.0f));
            aC[kc][3] = packh2(fmaxf(dC[j1][2] + b10, 0.0f), fmaxf(dC[j1][3] + b11, 0.0f));
        }

        // ---- L4: C1 @ W4 -> C2[.,64] ----
        float dD[8][4] = {};
        #pragma unroll
        for (int kc = 0; kc < 4; kc++) {
            #pragma unroll
            for (int j = 0; j < 8; j++) {
                unsigned b0 = LDU32(s_w4h, j * 8 + g2, kc * 16 + c2);
                unsigned b1 = LDU32(s_w4h, j * 8 + g2, kc * 16 + c2 + 8);
                mma16816(dD[j], aC[kc], b0, b1);
            }
        }
        unsigned aD[4][4];
        #pragma unroll
        for (int kc = 0; kc < 4; kc++) {
            const int j0 = 2 * kc, j1 = j0 + 1;
            const float b00 = s_b4[8 * j0 + c2], b01 = s_b4[8 * j0 + c2 + 1];
            const float b10 = s_b4[8 * j1 + c2], b11 = s_b4[8 * j1 + c2 + 1];
            aD[kc][0] = packh2(fmaxf(dD[j0][0] + b00, 0.0f), fmaxf(dD[j0][1] + b01, 0.0f));
            aD[kc][1] = packh2(fmaxf(dD[j0][2] + b00, 0.0f), fmaxf(dD[j0][3] + b01, 0.0f));
            aD[kc][2] = packh2(fmaxf(dD[j1][0] + b10, 0.0f), fmaxf(dD[j1][1] + b11, 0.0f));
            aD[kc][3] = packh2(fmaxf(dD[j1][2] + b10, 0.0f), fmaxf(dD[j1][3] + b11, 0.0f));
        }

        // ---- L5: C2 @ W5 -> colors (cols 0..2 of 8) ----
        float dO[4] = {};
        #pragma unroll
        for (int kc = 0; kc < 4; kc++) {
            unsigned b0 = LDU32(s_w5h, g2, kc * 16 + c2);
            unsigned b1 = LDU32(s_w5h, g2, kc * 16 + c2 + 8);
            mma16816(dO, aD[kc], b0, b1);
        }
        {
            float v0 = dO[0] + s_b5[c2], v1 = dO[1] + s_b5[c2 + 1];
            float v2 = dO[2] + s_b5[c2], v3 = dO[3] + s_b5[c2 + 1];
            v0 = 1.0f / (1.0f + __expf(-v0));
            v1 = 1.0f / (1.0f + __expf(-v1));
            v2 = 1.0f / (1.0f + __expf(-v2));
            v3 = 1.0f / (1.0f + __expf(-v3));
            const int p0 = blockIdx.x * NT + r0, p1 = p0 + 8;
            const bool m0 = s_mask[r0], m1 = s_mask[r8];
            if (c2 == 0) {          // cols 0,1
                if (p0 < N) { out[3 * p0 + 0] = m0 ? v0 : 0.0f; out[3 * p0 + 1] = m0 ? v1 : 0.0f; }
                if (p1 < N) { out[3 * p1 + 0] = m1 ? v2 : 0.0f; out[3 * p1 + 1] = m1 ? v3 : 0.0f; }
            } else if (c2 == 2) {   // col 2
                if (p0 < N) out[3 * p0 + 2] = m0 ? v0 : 0.0f;
                if (p1 < N) out[3 * p1 + 2] = m1 ? v2 : 0.0f;
            }
        }
    }
#undef LDU32
}

extern "C" void kernel_launch(void* const* d_in, const int* in_sizes, int n_in,
                              void* d_out, int out_size) {
    const float* x      = (const float*)d_in[0];
    const float* dirs   = (const float*)d_in[1];
    const float* tables = (const float*)d_in[2];
    const float* w1 = (const float*)d_in[3];
    const float* b1 = (const float*)d_in[4];
    const float* w2 = (const float*)d_in[5];
    const float* b2 = (const float*)d_in[6];
    const float* w3 = (const float*)d_in[7];
    const float* b3 = (const float*)d_in[8];
    const float* w4 = (const float*)d_in[9];
    const float* b4 = (const float*)d_in[10];
    const float* w5 = (const float*)d_in[11];
    const float* b5 = (const float*)d_in[12];
    float* out = (float*)d_out;

    const int N = in_sizes[0] / 3;
    const int blocks = (N + NT - 1) / NT;
    ngp_tc_kernel<<<blocks, NT>>>(x, dirs, tables,
                                  w1, b1, w2, b2, w3, b3, w4, b4, w5, b5,
                                  out, N);
}